// round 2
// baseline (speedup 1.0000x reference)
#include <cuda_runtime.h>

#define A_TOT   256
#define D_IN    39
#define H       50
#define ROWP    52          // padded weight row length (16B aligned rows)
#define HP      25          // 50/2 packed pairs
#define BLK     128         // threads per block
#define ROWS    256         // rows per block (2 per thread)
#define C0      20          // d-chunk widths (20 + 19 = 39)
#define C1      19
#define XPAD    21          // x tile row stride (odd -> conflict free)

typedef unsigned long long u64;

__device__ __forceinline__ u64 packpair(float lo, float hi) {
    u64 r; asm("mov.b64 %0, {%1, %2};" : "=l"(r) : "f"(lo), "f"(hi)); return r;
}
__device__ __forceinline__ u64 pack2(float v) {
    u64 r; asm("mov.b64 %0, {%1, %1};" : "=l"(r) : "f"(v)); return r;
}
__device__ __forceinline__ void unpack2(u64 v, float& lo, float& hi) {
    asm("mov.b64 {%0, %1}, %2;" : "=f"(lo), "=f"(hi) : "l"(v));
}
__device__ __forceinline__ u64 fma2(u64 a, u64 b, u64 c) {
    u64 d; asm("fma.rn.f32x2 %0, %1, %2, %3;" : "=l"(d) : "l"(a), "l"(b), "l"(c));
    return d;
}
__device__ __forceinline__ float silu_f(float v) {
    return __fdividef(v, 1.0f + __expf(-v));
}

// Layer-2 half: OFF/PAIRS/VEC compile-time; computes h2 for both rows over
// columns [OFF, OFF+2*PAIRS) and immediately folds silu(h2) . W3 into acc3.
template<int OFF, int PAIRS, int VEC>
__device__ __forceinline__ void layer2_half(const float* __restrict__ sW2,
                                            const float* __restrict__ sB2,
                                            const float* __restrict__ sW3,
                                            const float* __restrict__ hfa,
                                            const float* __restrict__ hfb,
                                            u64& acc3a, u64& acc3b)
{
    u64 a2a[PAIRS], a2b[PAIRS];
    const u64* bp = reinterpret_cast<const u64*>(&sB2[OFF]);
    #pragma unroll
    for (int p = 0; p < PAIRS; p++) { a2a[p] = bp[p]; a2b[p] = bp[p]; }

    #pragma unroll
    for (int d = 0; d < H; d++) {
        u64 xx0 = pack2(hfa[d]);
        u64 xx1 = pack2(hfb[d]);
        const ulonglong2* wv = reinterpret_cast<const ulonglong2*>(&sW2[d * ROWP + OFF]);
        #pragma unroll
        for (int q = 0; q < VEC; q++) {
            ulonglong2 w = wv[q];
            a2a[2*q]   = fma2(xx0, w.x, a2a[2*q]);
            a2b[2*q]   = fma2(xx1, w.x, a2b[2*q]);
            a2a[2*q+1] = fma2(xx0, w.y, a2a[2*q+1]);
            a2b[2*q+1] = fma2(xx1, w.y, a2b[2*q+1]);
        }
    }
    const u64* w3p = reinterpret_cast<const u64*>(&sW3[OFF]);
    #pragma unroll
    for (int p = 0; p < PAIRS; p++) {
        float lo, hi;
        unpack2(a2a[p], lo, hi);
        acc3a = fma2(packpair(silu_f(lo), silu_f(hi)), w3p[p], acc3a);
        unpack2(a2b[p], lo, hi);
        acc3b = fma2(packpair(silu_f(lo), silu_f(hi)), w3p[p], acc3b);
    }
}

__global__ __launch_bounds__(BLK, 3)
void atomic_mlp_kernel(const float* __restrict__ desc,
                       const int*   __restrict__ numbers,
                       const float* __restrict__ W1, const float* __restrict__ b1,
                       const float* __restrict__ W2, const float* __restrict__ b2,
                       const float* __restrict__ W3, const float* __restrict__ b3,
                       float* __restrict__ out, int N)
{
    __shared__ __align__(16) float sW1[D_IN * ROWP];   //  8112 B
    __shared__ __align__(16) float sW2[H * ROWP];      // 10400 B
    __shared__ __align__(16) float sB1[ROWP];
    __shared__ __align__(16) float sB2[ROWP];
    __shared__ __align__(16) float sW3[ROWP];
    __shared__ float sB3v;
    __shared__ __align__(16) float sx[ROWS * XPAD];    // 21504 B

    const int a = blockIdx.x;
    const int t = threadIdx.x;
    const int s = numbers[a];

    // ---- stage weights (zero pads) ----
    for (int i = t; i < D_IN * ROWP; i += BLK) {
        int d = i / ROWP, j = i - d * ROWP;
        sW1[i] = (j < H) ? W1[(s * D_IN + d) * H + j] : 0.0f;
    }
    for (int i = t; i < H * ROWP; i += BLK) {
        int d = i / ROWP, j = i - d * ROWP;
        sW2[i] = (j < H) ? W2[(s * H + d) * H + j] : 0.0f;
    }
    if (t < ROWP) {
        sB1[t] = (t < H) ? b1[s * H + t] : 0.0f;
        sB2[t] = (t < H) ? b2[s * H + t] : 0.0f;
        sW3[t] = (t < H) ? W3[s * H + t] : 0.0f;
    }
    if (t == 0) sB3v = b3[s];

    const size_t rowstride = (size_t)A_TOT * D_IN;
    const size_t base = ((size_t)blockIdx.y * ROWS) * rowstride + (size_t)a * D_IN;

    // ---- stage x chunk 0 (d in [0,20)) ----
    for (int i = t; i < ROWS * C0; i += BLK) {
        int r = i / C0, c = i - r * C0;
        sx[r * XPAD + c] = desc[base + (size_t)r * rowstride + c];
    }
    __syncthreads();

    // ================= layer 1 =================
    u64 h1a[HP], h1b[HP];
    {
        const u64* bp = reinterpret_cast<const u64*>(sB1);
        #pragma unroll
        for (int p = 0; p < HP; p++) { h1a[p] = bp[p]; h1b[p] = bp[p]; }
    }

    #pragma unroll
    for (int dd = 0; dd < C0; dd++) {
        u64 xx0 = pack2(sx[t * XPAD + dd]);
        u64 xx1 = pack2(sx[(t + BLK) * XPAD + dd]);
        const float* row = &sW1[dd * ROWP];
        const ulonglong2* wv = reinterpret_cast<const ulonglong2*>(row);
        #pragma unroll
        for (int p = 0; p < 12; p++) {
            ulonglong2 w = wv[p];
            h1a[2*p]   = fma2(xx0, w.x, h1a[2*p]);
            h1b[2*p]   = fma2(xx1, w.x, h1b[2*p]);
            h1a[2*p+1] = fma2(xx0, w.y, h1a[2*p+1]);
            h1b[2*p+1] = fma2(xx1, w.y, h1b[2*p+1]);
        }
        u64 wl = *reinterpret_cast<const u64*>(row + 48);
        h1a[24] = fma2(xx0, wl, h1a[24]);
        h1b[24] = fma2(xx1, wl, h1b[24]);
    }
    __syncthreads();

    // ---- stage x chunk 1 (d in [20,39)) ----
    for (int i = t; i < ROWS * C1; i += BLK) {
        int r = i / C1, c = i - r * C1;
        sx[r * XPAD + c] = desc[base + (size_t)r * rowstride + (C0 + c)];
    }
    __syncthreads();

    #pragma unroll
    for (int dd = 0; dd < C1; dd++) {
        u64 xx0 = pack2(sx[t * XPAD + dd]);
        u64 xx1 = pack2(sx[(t + BLK) * XPAD + dd]);
        const float* row = &sW1[(C0 + dd) * ROWP];
        const ulonglong2* wv = reinterpret_cast<const ulonglong2*>(row);
        #pragma unroll
        for (int p = 0; p < 12; p++) {
            ulonglong2 w = wv[p];
            h1a[2*p]   = fma2(xx0, w.x, h1a[2*p]);
            h1b[2*p]   = fma2(xx1, w.x, h1b[2*p]);
            h1a[2*p+1] = fma2(xx0, w.y, h1a[2*p+1]);
            h1b[2*p+1] = fma2(xx1, w.y, h1b[2*p+1]);
        }
        u64 wl = *reinterpret_cast<const u64*>(row + 48);
        h1a[24] = fma2(xx0, wl, h1a[24]);
        h1b[24] = fma2(xx1, wl, h1b[24]);
    }

    // ---- silu -> register-resident hidden activations for both rows ----
    float hfa[H], hfb[H];
    #pragma unroll
    for (int p = 0; p < HP; p++) {
        float lo, hi;
        unpack2(h1a[p], lo, hi);
        hfa[2*p] = silu_f(lo); hfa[2*p+1] = silu_f(hi);
        unpack2(h1b[p], lo, hi);
        hfb[2*p] = silu_f(lo); hfb[2*p+1] = silu_f(hi);
    }

    // ========== layers 2+3 (two column halves; layer3 fused per half) ==========
    u64 acc3a = 0ULL, acc3b = 0ULL;
    layer2_half< 0, 12, 6>(sW2, sB2, sW3, hfa, hfb, acc3a, acc3b);
    layer2_half<24, 14, 7>(sW2, sB2, sW3, hfa, hfb, acc3a, acc3b);

    float alo, ahi;
    const int n0 = blockIdx.y * ROWS + t;
    unpack2(acc3a, alo, ahi);
    out[(size_t)n0 * A_TOT + a] = alo + ahi + sB3v;
    unpack2(acc3b, alo, ahi);
    out[(size_t)(n0 + BLK) * A_TOT + a] = alo + ahi + sB3v;
}

extern "C" void kernel_launch(void* const* d_in, const int* in_sizes, int n_in,
                              void* d_out, int out_size)
{
    const float* desc    = (const float*)d_in[0];
    const int*   numbers = (const int*)  d_in[1];
    const float* W1      = (const float*)d_in[2];
    const float* b1      = (const float*)d_in[3];
    const float* W2      = (const float*)d_in[4];
    const float* b2      = (const float*)d_in[5];
    const float* W3      = (const float*)d_in[6];
    const float* b3      = (const float*)d_in[7];
    float* out = (float*)d_out;

    const int N = in_sizes[0] / (A_TOT * D_IN);   // 4096
    dim3 grid(A_TOT, N / ROWS);
    atomic_mlp_kernel<<<grid, BLK>>>(desc, numbers, W1, b1, W2, b2, W3, b3, out, N);
}

// round 4
// speedup vs baseline: 1.1267x; 1.1267x over previous
#include <cuda_runtime.h>
#include <cuda_bf16.h>
#include <cstdint>

typedef uint32_t u32;

#define A_TOT  256
#define D_IN   39
#define H      50
#define TILE_M 128
#define BLK    128
#define S1W    28          // layer-1 tile stride in 32-bit words (48 bf16 cols -> 24 used)
#define S2W    36          // layer-2 tile stride in words (64 bf16 cols -> 32 used)

// shared memory offsets in 32-bit words
#define O_XHI  0           // 128 x S2W  (4608 w) — x tile hi (layer1 uses S1W indexing)
#define O_XLO  4608        // 4608 w
#define O_BHI  9216        // 56 x S2W (2016 w)
#define O_BLO  11232       // 2016 w
#define O_RAW  13248       // 2500 w raw weight scratch
#define O_B1   15748       // 56
#define O_B2   15804       // 56
#define O_W3   15860       // 56
#define O_B3   15916       // 1
#define SMEM_WORDS 15920
#define SMEM_BYTES (SMEM_WORDS * 4)

__device__ __forceinline__ float silu_f(float v) {
    return __fdividef(v, 1.0f + __expf(-v));
}

// split two floats into packed bf16x2 hi-word and lo-word (x = hi + lo, ~16 mantissa bits)
__device__ __forceinline__ void split2(float v0, float v1, u32& hw, u32& lw) {
    float h0 = __bfloat162float(__float2bfloat16_rn(v0));
    float h1 = __bfloat162float(__float2bfloat16_rn(v1));
    __nv_bfloat162 hh = __floats2bfloat162_rn(h0, h1);          // exact repack
    __nv_bfloat162 ll = __floats2bfloat162_rn(v0 - h0, v1 - h1);
    hw = *reinterpret_cast<u32*>(&hh);
    lw = *reinterpret_cast<u32*>(&ll);
}

#define MMA(Cb, A0, A1, A2, A3, B0, B1)                                   \
    asm volatile("mma.sync.aligned.m16n8k16.row.col.f32.bf16.bf16.f32 "   \
                 "{%0,%1,%2,%3}, {%4,%5,%6,%7}, {%8,%9}, {%0,%1,%2,%3};"  \
                 : "+f"(Cb[0]), "+f"(Cb[1]), "+f"(Cb[2]), "+f"(Cb[3])     \
                 : "r"(A0), "r"(A1), "r"(A2), "r"(A3), "r"(B0), "r"(B1))

__global__ __launch_bounds__(BLK, 3)
void atomic_mlp_mma(const float* __restrict__ desc,
                    const int*   __restrict__ numbers,
                    const float* __restrict__ W1, const float* __restrict__ b1,
                    const float* __restrict__ W2, const float* __restrict__ b2,
                    const float* __restrict__ W3, const float* __restrict__ b3,
                    float* __restrict__ out)
{
    extern __shared__ __align__(16) u32 sm[];
    u32* XH = sm + O_XHI;
    u32* XL = sm + O_XLO;
    u32* BH = sm + O_BHI;
    u32* BL = sm + O_BLO;
    float* raw = (float*)(sm + O_RAW);
    float* b1v = (float*)(sm + O_B1);
    float* b2v = (float*)(sm + O_B2);
    float* w3v = (float*)(sm + O_W3);
    float* b3s = (float*)(sm + O_B3);

    const int t   = threadIdx.x;
    const int wid = t >> 5;
    const int lid = t & 31;
    const int g   = lid >> 2;   // groupID (row within 8-row group)
    const int tq  = lid & 3;    // thread-in-group (k / col quad)
    const int a   = blockIdx.x;
    const int s   = numbers[a];

    // ---- phase 0: prefetch W2 into regs; stage raw W1, biases, x1 ----
    float w2s[20];
    #pragma unroll
    for (int j = 0; j < 20; j++) {
        int i = t + j * BLK;
        w2s[j] = (i < H * H) ? W2[s * H * H + i] : 0.0f;
    }
    #pragma unroll
    for (int j = 0; j < 16; j++) {
        int i = t + j * BLK;
        if (i < D_IN * H) raw[i] = W1[s * D_IN * H + i];
    }
    if (t < 56) {
        b1v[t] = (t < H) ? b1[s * H + t] : 0.0f;
        b2v[t] = (t < H) ? b2[s * H + t] : 0.0f;
        w3v[t] = (t < H) ? W3[s * H + t] : 0.0f;
    }
    if (t == 0) b3s[0] = b3[s];

    // x1: 128 rows x 24 words (48 bf16 cols; cols>=39 zero)
    {
        const size_t rs   = (size_t)A_TOT * D_IN;
        const size_t base = ((size_t)blockIdx.y * TILE_M) * rs + (size_t)a * D_IN;
        #pragma unroll
        for (int j = 0; j < 24; j++) {
            int i = t + j * BLK;              // 0..3071
            int r = i / 24, w = i % 24;
            int c0 = 2 * w, c1 = c0 + 1;
            float v0 = (c0 < D_IN) ? desc[base + (size_t)r * rs + c0] : 0.0f;
            float v1 = (c1 < D_IN) ? desc[base + (size_t)r * rs + c1] : 0.0f;
            u32 hw, lw; split2(v0, v1, hw, lw);
            XH[r * S1W + w] = hw;
            XL[r * S1W + w] = lw;
        }
    }
    __syncthreads();

    // ---- B1 = W1^T (56 n-rows x 24 words), split hi/lo ----
    #pragma unroll
    for (int j = 0; j < 11; j++) {
        int i = t + j * BLK;
        if (i < 56 * 24) {
            int n = i / 24, w = i % 24;
            int k0 = 2 * w, k1 = k0 + 1;
            float v0 = (k0 < D_IN && n < H) ? raw[k0 * H + n] : 0.0f;
            float v1 = (k1 < D_IN && n < H) ? raw[k1 * H + n] : 0.0f;
            u32 hw, lw; split2(v0, v1, hw, lw);
            BH[n * S1W + w] = hw;
            BL[n * S1W + w] = lw;
        }
    }
    __syncthreads();

    // ---- layer 1 MMAs: M=32/warp, N=56, K=48 (3 passes hi/lo) ----
    float c[56];
    #pragma unroll
    for (int i = 0; i < 56; i++) c[i] = 0.0f;

    #pragma unroll
    for (int kk = 0; kk < 3; kk++) {
        const int kw = kk * 8;
        u32 ah[2][4], al[2][4];
        #pragma unroll
        for (int m = 0; m < 2; m++) {
            int r = wid * 32 + m * 16 + g;
            ah[m][0] = XH[r * S1W + kw + tq];
            ah[m][1] = XH[(r + 8) * S1W + kw + tq];
            ah[m][2] = XH[r * S1W + kw + tq + 4];
            ah[m][3] = XH[(r + 8) * S1W + kw + tq + 4];
            al[m][0] = XL[r * S1W + kw + tq];
            al[m][1] = XL[(r + 8) * S1W + kw + tq];
            al[m][2] = XL[r * S1W + kw + tq + 4];
            al[m][3] = XL[(r + 8) * S1W + kw + tq + 4];
        }
        #pragma unroll
        for (int n = 0; n < 7; n++) {
            int bb = (n * 8 + g) * S1W + kw + tq;
            u32 bh0 = BH[bb], bh1 = BH[bb + 4];
            u32 bl0 = BL[bb], bl1 = BL[bb + 4];
            #pragma unroll
            for (int m = 0; m < 2; m++) {
                float* C = &c[(m * 7 + n) * 4];
                MMA(C, ah[m][0], ah[m][1], ah[m][2], ah[m][3], bh0, bh1);
                MMA(C, ah[m][0], ah[m][1], ah[m][2], ah[m][3], bl0, bl1);
                MMA(C, al[m][0], al[m][1], al[m][2], al[m][3], bh0, bh1);
            }
        }
    }
    __syncthreads();   // everyone done reading x1 / B1

    // stash prefetched W2 to raw scratch
    #pragma unroll
    for (int j = 0; j < 20; j++) {
        int i = t + j * BLK;
        if (i < H * H) raw[i] = w2s[j];
    }

    // ---- epilogue 1: bias + silu + split -> x2 tile (stride S2W) ----
    #pragma unroll
    for (int m = 0; m < 2; m++) {
        #pragma unroll
        for (int n = 0; n < 7; n++) {
            int C0 = n * 8 + 2 * tq;
            float bia0 = b1v[C0], bia1 = b1v[C0 + 1];
            #pragma unroll
            for (int hh = 0; hh < 2; hh++) {
                int r = wid * 32 + m * 16 + g + hh * 8;
                float v0 = c[(m * 7 + n) * 4 + hh * 2 + 0] + bia0;
                float v1 = c[(m * 7 + n) * 4 + hh * 2 + 1] + bia1;
                float s0 = (C0     < H) ? silu_f(v0) : 0.0f;
                float s1 = (C0 + 1 < H) ? silu_f(v1) : 0.0f;
                u32 hw, lw; split2(s0, s1, hw, lw);
                XH[r * S2W + n * 4 + tq] = hw;
                XL[r * S2W + n * 4 + tq] = lw;
            }
        }
    }
    // zero x2 pad words 28..31 (bf16 cols 56..63)
    #pragma unroll
    for (int j = 0; j < 4; j++) {
        int i = t + j * BLK;            // 0..511
        int r = i >> 2, w = 28 + (i & 3);
        XH[r * S2W + w] = 0u;
        XL[r * S2W + w] = 0u;
    }
    __syncthreads();

    // ---- B2 = W2^T (56 x 32 words), split hi/lo ----
    #pragma unroll
    for (int j = 0; j < 14; j++) {
        int i = t + j * BLK;            // exactly 56*32 = 1792
        int n = i / 32, w = i % 32;
        int k0 = 2 * w, k1 = k0 + 1;
        float v0 = (k0 < H && n < H) ? raw[k0 * H + n] : 0.0f;
        float v1 = (k1 < H && n < H) ? raw[k1 * H + n] : 0.0f;
        u32 hw, lw; split2(v0, v1, hw, lw);
        BH[n * S2W + w] = hw;
        BL[n * S2W + w] = lw;
    }
    __syncthreads();

    // ---- layer 2 MMAs: K=64 (4 k-steps) ----
    #pragma unroll
    for (int i = 0; i < 56; i++) c[i] = 0.0f;

    #pragma unroll
    for (int kk = 0; kk < 4; kk++) {
        const int kw = kk * 8;
        u32 ah[2][4], al[2][4];
        #pragma unroll
        for (int m = 0; m < 2; m++) {
            int r = wid * 32 + m * 16 + g;
            ah[m][0] = XH[r * S2W + kw + tq];
            ah[m][1] = XH[(r + 8) * S2W + kw + tq];
            ah[m][2] = XH[r * S2W + kw + tq + 4];
            ah[m][3] = XH[(r + 8) * S2W + kw + tq + 4];
            al[m][0] = XL[r * S2W + kw + tq];
            al[m][1] = XL[(r + 8) * S2W + kw + tq];
            al[m][2] = XL[r * S2W + kw + tq + 4];
            al[m][3] = XL[(r + 8) * S2W + kw + tq + 4];
        }
        #pragma unroll
        for (int n = 0; n < 7; n++) {
            int bb = (n * 8 + g) * S2W + kw + tq;
            u32 bh0 = BH[bb], bh1 = BH[bb + 4];
            u32 bl0 = BL[bb], bl1 = BL[bb + 4];
            #pragma unroll
            for (int m = 0; m < 2; m++) {
                float* C = &c[(m * 7 + n) * 4];
                MMA(C, ah[m][0], ah[m][1], ah[m][2], ah[m][3], bh0, bh1);
                MMA(C, ah[m][0], ah[m][1], ah[m][2], ah[m][3], bl0, bl1);
                MMA(C, al[m][0], al[m][1], al[m][2], al[m][3], bh0, bh1);
            }
        }
    }

    // ---- epilogue 2: bias + silu, dot W3, lane-reduce, store ----
    float sum[4] = {0.0f, 0.0f, 0.0f, 0.0f};
    #pragma unroll
    for (int m = 0; m < 2; m++) {
        #pragma unroll
        for (int n = 0; n < 7; n++) {
            int C0 = n * 8 + 2 * tq;
            float bia0 = b2v[C0], bia1 = b2v[C0 + 1];
            float w30 = w3v[C0], w31 = w3v[C0 + 1];
            #pragma unroll
            for (int hh = 0; hh < 2; hh++) {
                float v0 = c[(m * 7 + n) * 4 + hh * 2 + 0] + bia0;
                float v1 = c[(m * 7 + n) * 4 + hh * 2 + 1] + bia1;
                sum[m * 2 + hh] += silu_f(v0) * w30 + silu_f(v1) * w31;
            }
        }
    }
    #pragma unroll
    for (int q = 0; q < 4; q++) {
        sum[q] += __shfl_xor_sync(0xffffffffu, sum[q], 1);
        sum[q] += __shfl_xor_sync(0xffffffffu, sum[q], 2);
    }
    if (tq == 0) {
        float bb = b3s[0];
        int nbase = blockIdx.y * TILE_M + wid * 32 + g;
        #pragma unroll
        for (int m = 0; m < 2; m++)
            #pragma unroll
            for (int hh = 0; hh < 2; hh++)
                out[(size_t)(nbase + m * 16 + hh * 8) * A_TOT + a] = sum[m * 2 + hh] + bb;
    }
}

extern "C" void kernel_launch(void* const* d_in, const int* in_sizes, int n_in,
                              void* d_out, int out_size)
{
    const float* desc    = (const float*)d_in[0];
    const int*   numbers = (const int*)  d_in[1];
    const float* W1      = (const float*)d_in[2];
    const float* b1      = (const float*)d_in[3];
    const float* W2      = (const float*)d_in[4];
    const float* b2      = (const float*)d_in[5];
    const float* W3      = (const float*)d_in[6];
    const float* b3      = (const float*)d_in[7];
    float* out = (float*)d_out;

    const int N = in_sizes[0] / (A_TOT * D_IN);   // 4096
    static int configured = 0;
    if (!configured) {
        cudaFuncSetAttribute(atomic_mlp_mma, cudaFuncAttributeMaxDynamicSharedMemorySize, SMEM_BYTES);
        configured = 1;
    }
    dim3 grid(A_TOT, N / TILE_M);
    atomic_mlp_mma<<<grid, BLK, SMEM_BYTES>>>(desc, numbers, W1, b1, W2, b2, W3, b3, out);
}

// round 5
// speedup vs baseline: 2.4478x; 2.1724x over previous
#include <cuda_runtime.h>
#include <cuda_bf16.h>
#include <cstdint>

typedef uint32_t u32;

#define A_TOT  256
#define D_IN   39
#define H      50
#define BLK    128
#define TPB    4            // row-tiles per block
#define S1W    28           // B1 stride in words (24 used)
#define S2W    36           // B2 stride in words (32 used)

__device__ __forceinline__ float silu_f(float v) {
    return __fdividef(v, 1.0f + __expf(-v));
}
__device__ __forceinline__ void split2(float v0, float v1, u32& hw, u32& lw) {
    float h0 = __bfloat162float(__float2bfloat16_rn(v0));
    float h1 = __bfloat162float(__float2bfloat16_rn(v1));
    __nv_bfloat162 hh = __floats2bfloat162_rn(h0, h1);
    __nv_bfloat162 ll = __floats2bfloat162_rn(v0 - h0, v1 - h1);
    hw = *reinterpret_cast<u32*>(&hh);
    lw = *reinterpret_cast<u32*>(&ll);
}

#define MMA(Cb, A0, A1, A2, A3, B0, B1)                                   \
    asm volatile("mma.sync.aligned.m16n8k16.row.col.f32.bf16.bf16.f32 "   \
                 "{%0,%1,%2,%3}, {%4,%5,%6,%7}, {%8,%9}, {%0,%1,%2,%3};"  \
                 : "+f"(Cb[0]), "+f"(Cb[1]), "+f"(Cb[2]), "+f"(Cb[3])     \
                 : "r"(A0), "r"(A1), "r"(A2), "r"(A3), "r"(B0), "r"(B1))

__global__ __launch_bounds__(BLK, 3)
void atomic_mlp_mma2(const float* __restrict__ desc,
                     const int*   __restrict__ numbers,
                     const float* __restrict__ W1, const float* __restrict__ b1,
                     const float* __restrict__ W2, const float* __restrict__ b2,
                     const float* __restrict__ W3, const float* __restrict__ b3,
                     float* __restrict__ out)
{
    __shared__ u32 sB1H[56 * S1W], sB1L[56 * S1W];     // 1568 w each
    __shared__ u32 sB2H[56 * S2W], sB2L[56 * S2W];     // 2016 w each
    __shared__ float sraw[D_IN * H + H * H];           // 4450 w
    __shared__ float b1v[56], b2v[56], w3v[56];
    __shared__ float b3s;

    const int t   = threadIdx.x;
    const int wid = t >> 5;
    const int lid = t & 31;
    const int g   = lid >> 2;
    const int tq  = lid & 3;
    const int a   = blockIdx.x;
    const int s   = numbers[a];

    // ---- stage raw weights (coalesced, once per block) ----
    #pragma unroll
    for (int j = 0; j < 16; j++) {
        int i = t + j * BLK;
        if (i < D_IN * H) sraw[i] = W1[s * D_IN * H + i];
    }
    #pragma unroll
    for (int j = 0; j < 20; j++) {
        int i = t + j * BLK;
        if (i < H * H) sraw[D_IN * H + i] = W2[s * H * H + i];
    }
    if (t < 56) {
        b1v[t] = (t < H) ? b1[s * H + t] : 0.0f;
        b2v[t] = (t < H) ? b2[s * H + t] : 0.0f;
        w3v[t] = (t < H) ? W3[s * H + t] : 0.0f;
    }
    if (t == 0) b3s = b3[s];
    __syncthreads();

    // ---- build split-transposed weight tiles ----
    #pragma unroll
    for (int j = 0; j < 11; j++) {
        int i = t + j * BLK;
        if (i < 56 * 24) {
            int n = i / 24, w = i % 24, k0 = 2 * w;
            float v0 = (k0     < D_IN && n < H) ? sraw[k0 * H + n]       : 0.0f;
            float v1 = (k0 + 1 < D_IN && n < H) ? sraw[(k0 + 1) * H + n] : 0.0f;
            u32 hw, lw; split2(v0, v1, hw, lw);
            sB1H[n * S1W + w] = hw;
            sB1L[n * S1W + w] = lw;
        }
    }
    #pragma unroll
    for (int j = 0; j < 14; j++) {
        int i = t + j * BLK;               // exactly 56*32
        int n = i / 32, w = i % 32, k0 = 2 * w;
        float v0 = (k0     < H && n < H) ? sraw[D_IN * H + k0 * H + n]       : 0.0f;
        float v1 = (k0 + 1 < H && n < H) ? sraw[D_IN * H + (k0 + 1) * H + n] : 0.0f;
        u32 hw, lw; split2(v0, v1, hw, lw);
        sB2H[n * S2W + w] = hw;
        sB2L[n * S2W + w] = lw;
    }
    __syncthreads();

    const size_t rs = (size_t)A_TOT * D_IN;
    const size_t acol = (size_t)a * D_IN;

    // ================= tile loop (barrier-free body) =================
    #pragma unroll 1
    for (int it = 0; it < TPB; it++) {
        const int R0 = (blockIdx.y * TPB + it) * 128 + wid * 32;

        // ---- load A1 straight to registers: 4 rows x 6 col-pairs ----
        // q = m*2+hh -> row R0 + m*16 + hh*8 + g
        float2 xv[4][3][2];
        #pragma unroll
        for (int q = 0; q < 4; q++) {
            int r = R0 + (q >> 1) * 16 + (q & 1) * 8 + g;
            const float* rp = desc + (size_t)r * rs + acol;
            xv[q][0][0] = make_float2(rp[2*tq],      rp[2*tq + 1]);
            xv[q][0][1] = make_float2(rp[8 + 2*tq],  rp[9 + 2*tq]);
            xv[q][1][0] = make_float2(rp[16 + 2*tq], rp[17 + 2*tq]);
            xv[q][1][1] = make_float2(rp[24 + 2*tq], rp[25 + 2*tq]);
            xv[q][2][0] = make_float2(rp[32 + 2*tq], (tq < 3) ? rp[33 + 2*tq] : 0.0f);
            xv[q][2][1] = make_float2(0.0f, 0.0f);
        }

        // ---- layer 1: C[128x56] += A[.,48] * B1^T, 3-pass bf16 split ----
        float c[56];
        #pragma unroll
        for (int i = 0; i < 56; i++) c[i] = 0.0f;

        #pragma unroll
        for (int kk = 0; kk < 3; kk++) {
            u32 ah[2][4], al[2][4];
            #pragma unroll
            for (int m = 0; m < 2; m++) {
                split2(xv[2*m][kk][0].x,   xv[2*m][kk][0].y,   ah[m][0], al[m][0]);
                split2(xv[2*m+1][kk][0].x, xv[2*m+1][kk][0].y, ah[m][1], al[m][1]);
                split2(xv[2*m][kk][1].x,   xv[2*m][kk][1].y,   ah[m][2], al[m][2]);
                split2(xv[2*m+1][kk][1].x, xv[2*m+1][kk][1].y, ah[m][3], al[m][3]);
            }
            #pragma unroll
            for (int n = 0; n < 7; n++) {
                int bb = (n * 8 + g) * S1W + kk * 8 + tq;
                u32 bh0 = sB1H[bb], bh1 = sB1H[bb + 4];
                u32 bl0 = sB1L[bb], bl1 = sB1L[bb + 4];
                #pragma unroll
                for (int m = 0; m < 2; m++) {
                    float* C = &c[(m * 7 + n) * 4];
                    MMA(C, ah[m][0], ah[m][1], ah[m][2], ah[m][3], bh0, bh1);
                    MMA(C, ah[m][0], ah[m][1], ah[m][2], ah[m][3], bl0, bl1);
                    MMA(C, al[m][0], al[m][1], al[m][2], al[m][3], bh0, bh1);
                }
            }
        }

        // ---- epilogue 1 in place: h = silu(c + b1)  (C layout == next A layout) ----
        #pragma unroll
        for (int m = 0; m < 2; m++)
            #pragma unroll
            for (int n = 0; n < 7; n++) {
                int col = n * 8 + 2 * tq;
                float bi0 = b1v[col], bi1 = b1v[col + 1];
                int idx = (m * 7 + n) * 4;
                c[idx]     = silu_f(c[idx]     + bi0);
                c[idx + 1] = silu_f(c[idx + 1] + bi1);
                c[idx + 2] = silu_f(c[idx + 2] + bi0);
                c[idx + 3] = silu_f(c[idx + 3] + bi1);
            }

        // ---- layer 2: C2 += h * B2^T, K=56 (4 k-steps, last half-padded) ----
        float c2[56];
        #pragma unroll
        for (int i = 0; i < 56; i++) c2[i] = 0.0f;

        #pragma unroll
        for (int kk = 0; kk < 4; kk++) {
            u32 ah[2][4], al[2][4];
            #pragma unroll
            for (int m = 0; m < 2; m++) {
                int c0 = (m * 7 + 2 * kk) * 4;
                split2(c[c0],     c[c0 + 1], ah[m][0], al[m][0]);
                split2(c[c0 + 2], c[c0 + 3], ah[m][1], al[m][1]);
                if (kk < 3) {
                    int c1 = (m * 7 + 2 * kk + 1) * 4;
                    split2(c[c1],     c[c1 + 1], ah[m][2], al[m][2]);
                    split2(c[c1 + 2], c[c1 + 3], ah[m][3], al[m][3]);
                } else {
                    ah[m][2] = ah[m][3] = al[m][2] = al[m][3] = 0u;
                }
            }
            #pragma unroll
            for (int n = 0; n < 7; n++) {
                int bb = (n * 8 + g) * S2W + kk * 8 + tq;
                u32 bh0 = sB2H[bb], bh1 = sB2H[bb + 4];
                u32 bl0 = sB2L[bb], bl1 = sB2L[bb + 4];
                #pragma unroll
                for (int m = 0; m < 2; m++) {
                    float* C = &c2[(m * 7 + n) * 4];
                    MMA(C, ah[m][0], ah[m][1], ah[m][2], ah[m][3], bh0, bh1);
                    MMA(C, ah[m][0], ah[m][1], ah[m][2], ah[m][3], bl0, bl1);
                    MMA(C, al[m][0], al[m][1], al[m][2], al[m][3], bh0, bh1);
                }
            }
        }

        // ---- epilogue 2: silu, dot W3, lane-reduce over tq, store ----
        float sum[4] = {0.0f, 0.0f, 0.0f, 0.0f};
        #pragma unroll
        for (int m = 0; m < 2; m++)
            #pragma unroll
            for (int n = 0; n < 7; n++) {
                int col = n * 8 + 2 * tq;
                float bi0 = b2v[col], bi1 = b2v[col + 1];
                float w30 = w3v[col], w31 = w3v[col + 1];
                int idx = (m * 7 + n) * 4;
                sum[m * 2 + 0] += silu_f(c2[idx]     + bi0) * w30
                                + silu_f(c2[idx + 1] + bi1) * w31;
                sum[m * 2 + 1] += silu_f(c2[idx + 2] + bi0) * w30
                                + silu_f(c2[idx + 3] + bi1) * w31;
            }
        #pragma unroll
        for (int q = 0; q < 4; q++) {
            sum[q] += __shfl_xor_sync(0xffffffffu, sum[q], 1);
            sum[q] += __shfl_xor_sync(0xffffffffu, sum[q], 2);
        }
        if (tq == 0) {
            float bb = b3s;
            #pragma unroll
            for (int q = 0; q < 4; q++) {
                int r = R0 + (q >> 1) * 16 + (q & 1) * 8 + g;
                out[(size_t)r * A_TOT + a] = sum[q] + bb;
            }
        }
    }
}

extern "C" void kernel_launch(void* const* d_in, const int* in_sizes, int n_in,
                              void* d_out, int out_size)
{
    const float* desc    = (const float*)d_in[0];
    const int*   numbers = (const int*)  d_in[1];
    const float* W1      = (const float*)d_in[2];
    const float* b1      = (const float*)d_in[3];
    const float* W2      = (const float*)d_in[4];
    const float* b2      = (const float*)d_in[5];
    const float* W3      = (const float*)d_in[6];
    const float* b3      = (const float*)d_in[7];
    float* out = (float*)d_out;

    const int N = in_sizes[0] / (A_TOT * D_IN);   // 4096
    dim3 grid(A_TOT, N / (128 * TPB));            // 256 x 8
    atomic_mlp_mma2<<<grid, BLK>>>(desc, numbers, W1, b1, W2, b2, W3, b3, out);
}

// round 6
// speedup vs baseline: 3.4435x; 1.4068x over previous
#include <cuda_runtime.h>
#include <cuda_fp16.h>
#include <cstdint>

typedef uint32_t u32;

#define A_TOT  256
#define D_IN   39
#define H      50
#define BLK    128
#define TPB    4            // row-tiles of 128 per block
#define S1W    24           // B1 row stride in words (24 used; 24 % 32 = 24 -> conflict-free LDS.64)
#define S2W    40           // B2 row stride in words (32 used; 40 % 32 = 8  -> conflict-free LDS.64)

__device__ __forceinline__ float silu_f(float v) {
    return __fdividef(v, 1.0f + __expf(-v));
}
__device__ __forceinline__ u32 pack_h2(float a, float b) {
    __half2 h = __floats2half2_rn(a, b);
    return *reinterpret_cast<u32*>(&h);
}
// weight split: v = hi + lo (fp16 each, ~22 effective mantissa bits)
__device__ __forceinline__ void wsplit2(float v0, float v1, u32& hw, u32& lw) {
    float h0 = __half2float(__float2half_rn(v0));
    float h1 = __half2float(__float2half_rn(v1));
    hw = pack_h2(h0, h1);
    lw = pack_h2(v0 - h0, v1 - h1);
}
// permute word within its 8-word k-group: [w0,w4,w1,w5,w2,w6,w3,w7]
// so lane tq's fragment pair (tq, tq+4) sits at 2*tq, 2*tq+1 -> one LDS.64
__device__ __forceinline__ int permw(int w) {
    int j = w & 7;
    return (w & ~7) + ((j & 3) * 2) + (j >> 2);
}

#define MMA(Cb, A0, A1, A2, A3, B0, B1)                                  \
    asm volatile("mma.sync.aligned.m16n8k16.row.col.f32.f16.f16.f32 "    \
                 "{%0,%1,%2,%3}, {%4,%5,%6,%7}, {%8,%9}, {%0,%1,%2,%3};" \
                 : "+f"(Cb[0]), "+f"(Cb[1]), "+f"(Cb[2]), "+f"(Cb[3])    \
                 : "r"(A0), "r"(A1), "r"(A2), "r"(A3), "r"(B0), "r"(B1))

__global__ __launch_bounds__(BLK, 3)
void atomic_mlp_mma3(const float* __restrict__ desc,
                     const int*   __restrict__ numbers,
                     const float* __restrict__ W1, const float* __restrict__ b1,
                     const float* __restrict__ W2, const float* __restrict__ b2,
                     const float* __restrict__ W3, const float* __restrict__ b3,
                     float* __restrict__ out)
{
    __shared__ __align__(16) u32 sB1H[56 * S1W], sB1L[56 * S1W];   // 5376 B each
    __shared__ __align__(16) u32 sB2H[56 * S2W], sB2L[56 * S2W];   // 8960 B each
    __shared__ float sraw[D_IN * H + H * H];                       // 17800 B
    __shared__ float b1v[56], b2v[56], w3v[56];
    __shared__ float b3s;

    const int t   = threadIdx.x;
    const int wid = t >> 5;
    const int lid = t & 31;
    const int g   = lid >> 2;
    const int tq  = lid & 3;
    const int a   = blockIdx.x;
    const int s   = numbers[a];

    const size_t rs   = (size_t)A_TOT * D_IN;
    const size_t acol = (size_t)a * D_IN;

    // ---- stage raw weights (coalesced, once per block) ----
    #pragma unroll
    for (int j = 0; j < 16; j++) {
        int i = t + j * BLK;
        if (i < D_IN * H) sraw[i] = W1[s * D_IN * H + i];
    }
    #pragma unroll
    for (int j = 0; j < 20; j++) {
        int i = t + j * BLK;
        if (i < H * H) sraw[D_IN * H + i] = W2[s * H * H + i];
    }
    if (t < 56) {
        b1v[t] = (t < H) ? b1[s * H + t] : 0.0f;
        b2v[t] = (t < H) ? b2[s * H + t] : 0.0f;
        w3v[t] = (t < H) ? W3[s * H + t] : 0.0f;
    }
    if (t == 0) b3s = b3[s];

    // ---- prefetch tile 0's A fragments (overlaps weight-tile build) ----
    float2 xv[4][3][2];
    {
        const int R0 = (blockIdx.y * TPB) * 128 + wid * 32;
        #pragma unroll
        for (int q = 0; q < 4; q++) {
            int r = R0 + (q >> 1) * 16 + (q & 1) * 8 + g;
            const float* rp = desc + (size_t)r * rs + acol;
            xv[q][0][0] = make_float2(rp[2*tq],      rp[2*tq + 1]);
            xv[q][0][1] = make_float2(rp[8 + 2*tq],  rp[9 + 2*tq]);
            xv[q][1][0] = make_float2(rp[16 + 2*tq], rp[17 + 2*tq]);
            xv[q][1][1] = make_float2(rp[24 + 2*tq], rp[25 + 2*tq]);
            xv[q][2][0] = make_float2(rp[32 + 2*tq], (tq < 3) ? rp[33 + 2*tq] : 0.0f);
            xv[q][2][1] = make_float2(0.0f, 0.0f);
        }
    }
    __syncthreads();

    // ---- build split-transposed, k-permuted weight tiles ----
    #pragma unroll
    for (int j = 0; j < 11; j++) {
        int i = t + j * BLK;
        if (i < 56 * 24) {
            int n = i / 24, w = i % 24, k0 = 2 * w;
            float v0 = (k0     < D_IN && n < H) ? sraw[k0 * H + n]       : 0.0f;
            float v1 = (k0 + 1 < D_IN && n < H) ? sraw[(k0 + 1) * H + n] : 0.0f;
            u32 hw, lw; wsplit2(v0, v1, hw, lw);
            int p = n * S1W + permw(w);
            sB1H[p] = hw;
            sB1L[p] = lw;
        }
    }
    #pragma unroll
    for (int j = 0; j < 14; j++) {
        int i = t + j * BLK;               // exactly 56*32
        int n = i / 32, w = i % 32, k0 = 2 * w;
        float v0 = (k0     < H && n < H) ? sraw[D_IN * H + k0 * H + n]       : 0.0f;
        float v1 = (k0 + 1 < H && n < H) ? sraw[D_IN * H + (k0 + 1) * H + n] : 0.0f;
        u32 hw, lw; wsplit2(v0, v1, hw, lw);
        int p = n * S2W + permw(w);
        sB2H[p] = hw;
        sB2L[p] = lw;
    }
    __syncthreads();

    // ================= tile loop (barrier-free body) =================
    #pragma unroll 1
    for (int it = 0; it < TPB; it++) {
        // ---- convert A1 fragments to fp16 (hi only; lo term dropped) ----
        u32 ah[3][2][4];
        #pragma unroll
        for (int kk = 0; kk < 3; kk++)
            #pragma unroll
            for (int m = 0; m < 2; m++) {
                ah[kk][m][0] = pack_h2(xv[2*m][kk][0].x,   xv[2*m][kk][0].y);
                ah[kk][m][1] = pack_h2(xv[2*m+1][kk][0].x, xv[2*m+1][kk][0].y);
                ah[kk][m][2] = pack_h2(xv[2*m][kk][1].x,   xv[2*m][kk][1].y);
                ah[kk][m][3] = pack_h2(xv[2*m+1][kk][1].x, xv[2*m+1][kk][1].y);
            }

        // ---- layer 1: C += Ahi*(Bhi + Blo) ----
        float c[56];
        #pragma unroll
        for (int i = 0; i < 56; i++) c[i] = 0.0f;

        #pragma unroll
        for (int kk = 0; kk < 3; kk++)
            #pragma unroll
            for (int n = 0; n < 7; n++) {
                int bb = (n * 8 + g) * S1W + kk * 8 + 2 * tq;
                uint2 bh = *reinterpret_cast<const uint2*>(&sB1H[bb]);
                uint2 bl = *reinterpret_cast<const uint2*>(&sB1L[bb]);
                #pragma unroll
                for (int m = 0; m < 2; m++) {
                    float* C = &c[(m * 7 + n) * 4];
                    MMA(C, ah[kk][m][0], ah[kk][m][1], ah[kk][m][2], ah[kk][m][3], bh.x, bh.y);
                    MMA(C, ah[kk][m][0], ah[kk][m][1], ah[kk][m][2], ah[kk][m][3], bl.x, bl.y);
                }
            }

        // ---- epilogue 1: h = silu(c + b1) -> fp16 A2 fragments in regs ----
        // (padded cols n>=50: B1 rows zero & b1v zero => c=0 => silu(0)=0)
        u32 ch0[14], ch1[14];
        #pragma unroll
        for (int m = 0; m < 2; m++)
            #pragma unroll
            for (int n = 0; n < 7; n++) {
                int col = n * 8 + 2 * tq;
                float bi0 = b1v[col], bi1 = b1v[col + 1];
                int idx = (m * 7 + n) * 4;
                ch0[m * 7 + n] = pack_h2(silu_f(c[idx]     + bi0), silu_f(c[idx + 1] + bi1));
                ch1[m * 7 + n] = pack_h2(silu_f(c[idx + 2] + bi0), silu_f(c[idx + 3] + bi1));
            }

        // ---- prefetch next tile's A (hidden behind layer-2 MMAs) ----
        if (it + 1 < TPB) {
            const int R0n = (blockIdx.y * TPB + it + 1) * 128 + wid * 32;
            #pragma unroll
            for (int q = 0; q < 4; q++) {
                int r = R0n + (q >> 1) * 16 + (q & 1) * 8 + g;
                const float* rp = desc + (size_t)r * rs + acol;
                xv[q][0][0] = make_float2(rp[2*tq],      rp[2*tq + 1]);
                xv[q][0][1] = make_float2(rp[8 + 2*tq],  rp[9 + 2*tq]);
                xv[q][1][0] = make_float2(rp[16 + 2*tq], rp[17 + 2*tq]);
                xv[q][1][1] = make_float2(rp[24 + 2*tq], rp[25 + 2*tq]);
                xv[q][2][0] = make_float2(rp[32 + 2*tq], (tq < 3) ? rp[33 + 2*tq] : 0.0f);
                xv[q][2][1] = make_float2(0.0f, 0.0f);
            }
        }

        // ---- layer 2: C2 += h_hi*(B2hi + B2lo), K=64 (kk=3 upper half zero) ----
        float c2[56];
        #pragma unroll
        for (int i = 0; i < 56; i++) c2[i] = 0.0f;

        #pragma unroll
        for (int kk = 0; kk < 4; kk++) {
            u32 a0[2], a1[2], a2[2], a3[2];
            #pragma unroll
            for (int m = 0; m < 2; m++) {
                a0[m] = ch0[m * 7 + 2 * kk];
                a1[m] = ch1[m * 7 + 2 * kk];
                if (kk < 3) {
                    a2[m] = ch0[m * 7 + 2 * kk + 1];
                    a3[m] = ch1[m * 7 + 2 * kk + 1];
                } else {
                    a2[m] = 0u; a3[m] = 0u;
                }
            }
            #pragma unroll
            for (int n = 0; n < 7; n++) {
                int bb = (n * 8 + g) * S2W + kk * 8 + 2 * tq;
                uint2 bh = *reinterpret_cast<const uint2*>(&sB2H[bb]);
                uint2 bl = *reinterpret_cast<const uint2*>(&sB2L[bb]);
                #pragma unroll
                for (int m = 0; m < 2; m++) {
                    float* C = &c2[(m * 7 + n) * 4];
                    MMA(C, a0[m], a1[m], a2[m], a3[m], bh.x, bh.y);
                    MMA(C, a0[m], a1[m], a2[m], a3[m], bl.x, bl.y);
                }
            }
        }

        // ---- epilogue 2: silu, dot W3, reduce over tq, store ----
        float sum[4] = {0.0f, 0.0f, 0.0f, 0.0f};
        #pragma unroll
        for (int m = 0; m < 2; m++)
            #pragma unroll
            for (int n = 0; n < 7; n++) {
                int col = n * 8 + 2 * tq;
                float bi0 = b2v[col], bi1 = b2v[col + 1];
                float w30 = w3v[col], w31 = w3v[col + 1];
                int idx = (m * 7 + n) * 4;
                sum[m * 2 + 0] += silu_f(c2[idx]     + bi0) * w30
                                + silu_f(c2[idx + 1] + bi1) * w31;
                sum[m * 2 + 1] += silu_f(c2[idx + 2] + bi0) * w30
                                + silu_f(c2[idx + 3] + bi1) * w31;
            }
        #pragma unroll
        for (int q = 0; q < 4; q++) {
            sum[q] += __shfl_xor_sync(0xffffffffu, sum[q], 1);
            sum[q] += __shfl_xor_sync(0xffffffffu, sum[q], 2);
        }
        if (tq == 0) {
            const int R0 = (blockIdx.y * TPB + it) * 128 + wid * 32;
            float bb = b3s;
            #pragma unroll
            for (int q = 0; q < 4; q++) {
                int r = R0 + (q >> 1) * 16 + (q & 1) * 8 + g;
                out[(size_t)r * A_TOT + a] = sum[q] + bb;
            }
        }
    }
}

extern "C" void kernel_launch(void* const* d_in, const int* in_sizes, int n_in,
                              void* d_out, int out_size)
{
    const float* desc    = (const float*)d_in[0];
    const int*   numbers = (const int*)  d_in[1];
    const float* W1      = (const float*)d_in[2];
    const float* b1      = (const float*)d_in[3];
    const float* W2      = (const float*)d_in[4];
    const float* b2      = (const float*)d_in[5];
    const float* W3      = (const float*)d_in[6];
    const float* b3      = (const float*)d_in[7];
    float* out = (float*)d_out;

    const int N = in_sizes[0] / (A_TOT * D_IN);   // 4096
    dim3 grid(A_TOT, N / (128 * TPB));            // 256 x 8
    atomic_mlp_mma3<<<grid, BLK>>>(desc, numbers, W1, b1, W2, b2, W3, b3, out);
}

// round 7
// speedup vs baseline: 3.6369x; 1.0562x over previous
#include <cuda_runtime.h>
#include <cuda_fp16.h>
#include <cstdint>

typedef uint32_t u32;

#define A_TOT  256
#define D_IN   39
#define H      50
#define BLK    128
#define TPB    4            // row-tiles of 128 per block
#define S1I    48           // interleaved B1 row stride in words (48 used; 48 % 32 == 16 -> conflict-free LDS.128)
#define S2I    80           // interleaved B2 row stride in words (64 used; 80 % 32 == 16 -> conflict-free LDS.128)

__device__ __forceinline__ u32 pack_h2(float a, float b) {
    __half2 h = __floats2half2_rn(a, b);
    return *reinterpret_cast<u32*>(&h);
}
__device__ __forceinline__ u32 h2mul(u32 a, u32 b) {
    __half2 r = __hmul2(*reinterpret_cast<__half2*>(&a), *reinterpret_cast<__half2*>(&b));
    return *reinterpret_cast<u32*>(&r);
}
__device__ __forceinline__ u32 h2add(u32 a, u32 b) {
    __half2 r = __hadd2(*reinterpret_cast<__half2*>(&a), *reinterpret_cast<__half2*>(&b));
    return *reinterpret_cast<u32*>(&r);
}
__device__ __forceinline__ u32 h2tanh(u32 a) {
    u32 d; asm("tanh.approx.f16x2 %0, %1;" : "=r"(d) : "r"(a)); return d;
}
// packed silu from half-scaled inputs: given hv = pack(v0/2, v1/2),
// silu(v) = (v/2) * (1 + tanh(v/2))
__device__ __forceinline__ u32 silu_h2_prescaled(u32 hv) {
    const u32 one2 = 0x3C003C00u;
    return h2mul(hv, h2add(one2, h2tanh(hv)));
}
// weight split: v = hi + lo (fp16 each, ~22 effective mantissa bits)
__device__ __forceinline__ void wsplit2(float v0, float v1, u32& hw, u32& lw) {
    float h0 = __half2float(__float2half_rn(v0));
    float h1 = __half2float(__float2half_rn(v1));
    hw = pack_h2(h0, h1);
    lw = pack_h2(v0 - h0, v1 - h1);
}

#define MMA(Cb, A0, A1, A2, A3, B0, B1)                                  \
    asm volatile("mma.sync.aligned.m16n8k16.row.col.f32.f16.f16.f32 "    \
                 "{%0,%1,%2,%3}, {%4,%5,%6,%7}, {%8,%9}, {%0,%1,%2,%3};" \
                 : "+f"(Cb[0]), "+f"(Cb[1]), "+f"(Cb[2]), "+f"(Cb[3])    \
                 : "r"(A0), "r"(A1), "r"(A2), "r"(A3), "r"(B0), "r"(B1))

__global__ __launch_bounds__(BLK, 4)
void atomic_mlp_mma4(const float* __restrict__ desc,
                     const int*   __restrict__ numbers,
                     const float* __restrict__ W1, const float* __restrict__ b1,
                     const float* __restrict__ W2, const float* __restrict__ b2,
                     const float* __restrict__ W3, const float* __restrict__ b3,
                     float* __restrict__ out)
{
    __shared__ __align__(16) u32 sB1[56 * S1I];        // 10752 B (hi/lo interleaved)
    __shared__ __align__(16) u32 sB2[56 * S2I];        // 17920 B
    __shared__ float sraw[D_IN * H + H * H];           // 17800 B
    __shared__ float b1h[56], b2h[56], w3v[56];        // b1h/b2h are 0.5-prescaled
    __shared__ float b3s;

    const int t   = threadIdx.x;
    const int wid = t >> 5;
    const int lid = t & 31;
    const int g   = lid >> 2;
    const int tq  = lid & 3;
    const int a   = blockIdx.x;
    const int s   = numbers[a];

    const size_t rs   = (size_t)A_TOT * D_IN;
    const size_t acol = (size_t)a * D_IN;

    // ---- stage raw weights (coalesced, once per block) ----
    #pragma unroll
    for (int j = 0; j < 16; j++) {
        int i = t + j * BLK;
        if (i < D_IN * H) sraw[i] = W1[s * D_IN * H + i];
    }
    #pragma unroll
    for (int j = 0; j < 20; j++) {
        int i = t + j * BLK;
        if (i < H * H) sraw[D_IN * H + i] = W2[s * H * H + i];
    }
    if (t < 56) {
        b1h[t] = (t < H) ? 0.5f * b1[s * H + t] : 0.0f;
        b2h[t] = (t < H) ? 0.5f * b2[s * H + t] : 0.0f;
        w3v[t] = (t < H) ? W3[s * H + t] : 0.0f;
    }
    if (t == 0) b3s = b3[s];

    // ---- prefetch tile 0's A fragments, packed fp16 (overlaps tile build) ----
    // ah[kk][m][o] layout: o in {0,1} = rows q=2m / 2m+1 first k-half; {2,3} second k-half
    u32 ahn[3][2][4];
    {
        const int R0 = (blockIdx.y * TPB) * 128 + wid * 32;
        #pragma unroll
        for (int q = 0; q < 4; q++) {
            int r = R0 + (q >> 1) * 16 + (q & 1) * 8 + g;
            const float* rp = desc + (size_t)r * rs + acol;
            int m = q >> 1, o = q & 1;
            ahn[0][m][o]     = pack_h2(rp[2*tq],      rp[2*tq + 1]);
            ahn[0][m][2 + o] = pack_h2(rp[8 + 2*tq],  rp[9 + 2*tq]);
            ahn[1][m][o]     = pack_h2(rp[16 + 2*tq], rp[17 + 2*tq]);
            ahn[1][m][2 + o] = pack_h2(rp[24 + 2*tq], rp[25 + 2*tq]);
            ahn[2][m][o]     = pack_h2(rp[32 + 2*tq], (tq < 3) ? rp[33 + 2*tq] : 0.0f);
            ahn[2][m][2 + o] = 0u;
        }
    }
    __syncthreads();

    // ---- build split-transposed, interleaved weight tiles ----
    // word w (pair of k) of row n lands at kk*16 + (w&3)*4 + (w>>2 & 1); lo at +2
    #pragma unroll
    for (int j = 0; j < 11; j++) {
        int i = t + j * BLK;
        if (i < 56 * 24) {
            int n = i / 24, w = i % 24, k0 = 2 * w;
            float v0 = (k0     < D_IN && n < H) ? sraw[k0 * H + n]       : 0.0f;
            float v1 = (k0 + 1 < D_IN && n < H) ? sraw[(k0 + 1) * H + n] : 0.0f;
            u32 hw, lw; wsplit2(v0, v1, hw, lw);
            int kk = w >> 3, jj = w & 7;
            int p = n * S1I + kk * 16 + (jj & 3) * 4 + (jj >> 2);
            sB1[p]     = hw;
            sB1[p + 2] = lw;
        }
    }
    #pragma unroll
    for (int j = 0; j < 14; j++) {
        int i = t + j * BLK;               // exactly 56*32
        int n = i / 32, w = i % 32, k0 = 2 * w;
        float v0 = (k0     < H && n < H) ? sraw[D_IN * H + k0 * H + n]       : 0.0f;
        float v1 = (k0 + 1 < H && n < H) ? sraw[D_IN * H + (k0 + 1) * H + n] : 0.0f;
        u32 hw, lw; wsplit2(v0, v1, hw, lw);
        int kk = w >> 3, jj = w & 7;
        int p = n * S2I + kk * 16 + (jj & 3) * 4 + (jj >> 2);
        sB2[p]     = hw;
        sB2[p + 2] = lw;
    }
    __syncthreads();

    // ================= tile loop (barrier-free body) =================
    #pragma unroll 1
    for (int it = 0; it < TPB; it++) {
        u32 ah[3][2][4];
        #pragma unroll
        for (int kk = 0; kk < 3; kk++)
            #pragma unroll
            for (int m = 0; m < 2; m++)
                #pragma unroll
                for (int o = 0; o < 4; o++)
                    ah[kk][m][o] = ahn[kk][m][o];

        // ---- layer 1: C += Ahi*(Bhi + Blo), one LDS.128 per (n,kk) ----
        float c[56];
        #pragma unroll
        for (int i = 0; i < 56; i++) c[i] = 0.0f;

        #pragma unroll
        for (int kk = 0; kk < 3; kk++)
            #pragma unroll
            for (int n = 0; n < 7; n++) {
                const uint4 b = *reinterpret_cast<const uint4*>(
                    &sB1[(n * 8 + g) * S1I + kk * 16 + 4 * tq]);
                #pragma unroll
                for (int m = 0; m < 2; m++) {
                    float* C = &c[(m * 7 + n) * 4];
                    MMA(C, ah[kk][m][0], ah[kk][m][1], ah[kk][m][2], ah[kk][m][3], b.x, b.y);
                    MMA(C, ah[kk][m][0], ah[kk][m][1], ah[kk][m][2], ah[kk][m][3], b.z, b.w);
                }
            }

        // ---- epilogue 1: h = silu(c + b1) via packed tanh -> fp16 A2 frags ----
        // (pad cols n>=50: B1 rows & b1h zero => c=0 => silu(0)=0)
        u32 ch0[14], ch1[14];
        #pragma unroll
        for (int m = 0; m < 2; m++)
            #pragma unroll
            for (int n = 0; n < 7; n++) {
                int col = n * 8 + 2 * tq;
                float bi0 = b1h[col], bi1 = b1h[col + 1];
                int idx = (m * 7 + n) * 4;
                ch0[m * 7 + n] = silu_h2_prescaled(
                    pack_h2(fmaf(0.5f, c[idx],     bi0), fmaf(0.5f, c[idx + 1], bi1)));
                ch1[m * 7 + n] = silu_h2_prescaled(
                    pack_h2(fmaf(0.5f, c[idx + 2], bi0), fmaf(0.5f, c[idx + 3], bi1)));
            }

        // ---- prefetch next tile's A (hidden behind layer-2 MMAs) ----
        if (it + 1 < TPB) {
            const int R0n = (blockIdx.y * TPB + it + 1) * 128 + wid * 32;
            #pragma unroll
            for (int q = 0; q < 4; q++) {
                int r = R0n + (q >> 1) * 16 + (q & 1) * 8 + g;
                const float* rp = desc + (size_t)r * rs + acol;
                int m = q >> 1, o = q & 1;
                ahn[0][m][o]     = pack_h2(rp[2*tq],      rp[2*tq + 1]);
                ahn[0][m][2 + o] = pack_h2(rp[8 + 2*tq],  rp[9 + 2*tq]);
                ahn[1][m][o]     = pack_h2(rp[16 + 2*tq], rp[17 + 2*tq]);
                ahn[1][m][2 + o] = pack_h2(rp[24 + 2*tq], rp[25 + 2*tq]);
                ahn[2][m][o]     = pack_h2(rp[32 + 2*tq], (tq < 3) ? rp[33 + 2*tq] : 0.0f);
                ahn[2][m][2 + o] = 0u;
            }
        }

        // ---- layer 2: C2 += h*(B2hi + B2lo), K=64 (kk=3 upper half zero) ----
        float c2[56];
        #pragma unroll
        for (int i = 0; i < 56; i++) c2[i] = 0.0f;

        #pragma unroll
        for (int kk = 0; kk < 4; kk++) {
            u32 a0[2], a1[2], a2[2], a3[2];
            #pragma unroll
            for (int m = 0; m < 2; m++) {
                a0[m] = ch0[m * 7 + 2 * kk];
                a1[m] = ch1[m * 7 + 2 * kk];
                if (kk < 3) {
                    a2[m] = ch0[m * 7 + 2 * kk + 1];
                    a3[m] = ch1[m * 7 + 2 * kk + 1];
                } else {
                    a2[m] = 0u; a3[m] = 0u;
                }
            }
            #pragma unroll
            for (int n = 0; n < 7; n++) {
                const uint4 b = *reinterpret_cast<const uint4*>(
                    &sB2[(n * 8 + g) * S2I + kk * 16 + 4 * tq]);
                #pragma unroll
                for (int m = 0; m < 2; m++) {
                    float* C = &c2[(m * 7 + n) * 4];
                    MMA(C, a0[m], a1[m], a2[m], a3[m], b.x, b.y);
                    MMA(C, a0[m], a1[m], a2[m], a3[m], b.z, b.w);
                }
            }
        }

        // ---- epilogue 2: packed-tanh silu, dot W3 in fp32, reduce, store ----
        float sum[4] = {0.0f, 0.0f, 0.0f, 0.0f};
        #pragma unroll
        for (int m = 0; m < 2; m++)
            #pragma unroll
            for (int n = 0; n < 7; n++) {
                int col = n * 8 + 2 * tq;
                float bi0 = b2h[col], bi1 = b2h[col + 1];
                float w30 = w3v[col], w31 = w3v[col + 1];
                int idx = (m * 7 + n) * 4;
                u32 h0 = silu_h2_prescaled(
                    pack_h2(fmaf(0.5f, c2[idx],     bi0), fmaf(0.5f, c2[idx + 1], bi1)));
                u32 h1 = silu_h2_prescaled(
                    pack_h2(fmaf(0.5f, c2[idx + 2], bi0), fmaf(0.5f, c2[idx + 3], bi1)));
                __half2 H0 = *reinterpret_cast<__half2*>(&h0);
                __half2 H1 = *reinterpret_cast<__half2*>(&h1);
                sum[m * 2 + 0] += __low2float(H0) * w30 + __high2float(H0) * w31;
                sum[m * 2 + 1] += __low2float(H1) * w30 + __high2float(H1) * w31;
            }
        #pragma unroll
        for (int q = 0; q < 4; q++) {
            sum[q] += __shfl_xor_sync(0xffffffffu, sum[q], 1);
            sum[q] += __shfl_xor_sync(0xffffffffu, sum[q], 2);
        }
        if (tq == 0) {
            const int R0 = (blockIdx.y * TPB + it) * 128 + wid * 32;
            float bb = b3s;
            #pragma unroll
            for (int q = 0; q < 4; q++) {
                int r = R0 + (q >> 1) * 16 + (q & 1) * 8 + g;
                out[(size_t)r * A_TOT + a] = sum[q] + bb;
            }
        }
    }
}

extern "C" void kernel_launch(void* const* d_in, const int* in_sizes, int n_in,
                              void* d_out, int out_size)
{
    const float* desc    = (const float*)d_in[0];
    const int*   numbers = (const int*)  d_in[1];
    const float* W1      = (const float*)d_in[2];
    const float* b1      = (const float*)d_in[3];
    const float* W2      = (const float*)d_in[4];
    const float* b2      = (const float*)d_in[5];
    const float* W3      = (const float*)d_in[6];
    const float* b3      = (const float*)d_in[7];
    float* out = (float*)d_out;

    const int N = in_sizes[0] / (A_TOT * D_IN);   // 4096
    dim3 grid(A_TOT, N / (128 * TPB));            // 256 x 8
    atomic_mlp_mma4<<<grid, BLK>>>(desc, numbers, W1, b1, W2, b2, W3, b3, out);
}